// round 11
// baseline (speedup 1.0000x reference)
#include <cuda_runtime.h>
#include <cuda_fp16.h>
#include <math.h>
#include <stdint.h>

#define NDIRS 5
#define NE    16
#define NW    3
#define ND    128
#define NP    256
#define NB    4
#define WK    768
#define MT    64          // rows per CTA (4 warps x 16)
#define NT    128         // threads per CTA
#define KC    64
#define NCH   (WK/KC)     // 12 chunks per x
#define NG    (NDIRS*NCH) // 60 global chunks
#define NST   3
#define LOG2E 1.4426950408889634f

struct RoutesP { int ve[NE][NW]; };

// V as fp16, [x][e][b][p][d] (elementwise convert, same layout as V)
__device__ __align__(16) __half g_v16[(size_t)NDIRS*NE*NB*NP*ND];

// ---------------- dynamic smem layout ----------------
// stage s: [KC][128] fp16 tile (16KB), XOR-swizzled 16B chunks
#define SM_V(s)   ((s)*16384)
#define SM_S      (NST*16384)          // f32[768]
#define SM_Q      (SM_S + 3072)        // f32[64]
#define SM_MX     (SM_Q + 256)         // f32[64]
#define SM_RED    (SM_MX + 256)        // f32[8]
#define SM_MM     (SM_RED + 32)        // f32[2]
#define SMEM_TOTAL (SM_MM + 32)        // ~52.8 KB

// ---------------- helpers ----------------
__device__ __forceinline__ uint32_t smem_u32(const void* p){
    uint32_t a;
    asm("{ .reg .u64 t; cvta.to.shared.u64 t, %1; cvt.u32.u64 %0, t; }" : "=r"(a) : "l"(p));
    return a;
}
__device__ __forceinline__ float ex2f(float x){
    float r; asm("ex2.approx.ftz.f32 %0, %1;" : "=f"(r) : "f"(x)); return r;
}
// pack two f32 -> f16x2 (lo=a, hi=b)
__device__ __forceinline__ uint32_t pack_h2(float a, float b){
    uint32_t r;
    asm("cvt.rn.f16x2.f32 %0, %2, %1;" : "=r"(r) : "f"(a), "f"(b));
    return r;
}
__device__ __forceinline__ void ldsm4t(uint32_t& r0, uint32_t& r1, uint32_t& r2, uint32_t& r3,
                                       uint32_t addr){
    asm volatile("ldmatrix.sync.aligned.m8n8.x4.trans.shared.b16 {%0,%1,%2,%3}, [%4];"
                 : "=r"(r0), "=r"(r1), "=r"(r2), "=r"(r3) : "r"(addr));
}
__device__ __forceinline__ void mma16816(float* c,
                                         uint32_t a0, uint32_t a1, uint32_t a2, uint32_t a3,
                                         uint32_t b0, uint32_t b1){
    asm volatile("mma.sync.aligned.m16n8k16.row.col.f32.f16.f16.f32 "
                 "{%0,%1,%2,%3}, {%4,%5,%6,%7}, {%8,%9}, {%0,%1,%2,%3};"
                 : "+f"(c[0]), "+f"(c[1]), "+f"(c[2]), "+f"(c[3])
                 : "r"(a0), "r"(a1), "r"(a2), "r"(a3), "r"(b0), "r"(b1));
}
__device__ __forceinline__ void cp16(uint32_t dst, const void* src){
    asm volatile("cp.async.cg.shared.global [%0], [%1], 16;" :: "r"(dst), "l"(src));
}
__device__ __forceinline__ void cp_commit(){ asm volatile("cp.async.commit_group;" ::: "memory"); }
template<int N> __device__ __forceinline__ void cp_wait(){
    asm volatile("cp.async.wait_group %0;" :: "n"(N) : "memory");
}

// stage a KC x 128 fp16 chunk into smem stage st with 16B-chunk XOR swizzle
__device__ __forceinline__ void issue_chunk(uint32_t smb, int st,
                                            const __half* __restrict__ src,
                                            int tid){
    #pragma unroll
    for (int i = 0; i < 8; i++){
        int cid = tid + i * NT;               // 0..1023 16B chunks
        int row = cid >> 4, c = cid & 15;
        uint32_t soff = (uint32_t)(row * 256 + ((c ^ (row & 7)) << 4));
        cp16(smb + SM_V(st) + soff, src + row * ND + c * 8);
    }
}

// ---------------- pre-kernel: elementwise V -> fp16 ----------------
__global__ __launch_bounds__(256)
void vsplit_kernel(const float* __restrict__ V){
    size_t i = ((size_t)blockIdx.x * 256 + threadIdx.x) * 8;
    float4 v0 = *(const float4*)(V + i);
    float4 v1 = *(const float4*)(V + i + 4);
    uint4 o;
    o.x = pack_h2(v0.x, v0.y);
    o.y = pack_h2(v0.z, v0.w);
    o.z = pack_h2(v1.x, v1.y);
    o.w = pack_h2(v1.z, v1.w);
    *(uint4*)((char*)g_v16 + i * 2) = o;
}

// ---------------- main kernel ----------------
__global__ __launch_bounds__(NT, 2)
void cantor_attn_mma(const float* __restrict__ Q,
                     const float* __restrict__ Kf,
                     const float* __restrict__ betas,
                     const float* __restrict__ temp,
                     const float* __restrict__ fw,
                     float* __restrict__ out,
                     RoutesP rp)
{
    extern __shared__ char sm[];
    const uint32_t smb = smem_u32(sm);
    float* sS  = (float*)(sm + SM_S);
    float* sQ  = (float*)(sm + SM_Q);
    float* sMx = (float*)(sm + SM_MX);
    float* sRed= (float*)(sm + SM_RED);
    float* sMM = (float*)(sm + SM_MM);

    const int tid  = threadIdx.x;
    const int lane = tid & 31;
    const int wid  = tid >> 5;          // 4 warps, warp wid owns rows wid*16..+15
    const int e  = blockIdx.z;
    const int b  = blockIdx.y;
    const int m0 = blockIdx.x * MT;

    const float invtemp = 1.0f / (fabsf(temp[0]) + 1e-6f);

    // fusion softmax weights
    float fwv[NDIRS], fm = -1e30f;
    #pragma unroll
    for (int x = 0; x < NDIRS; x++){ fwv[x] = fw[x]; fm = fmaxf(fm, fwv[x]); }
    float fsum = 0.0f;
    #pragma unroll
    for (int x = 0; x < NDIRS; x++){ fwv[x] = __expf(fwv[x] - fm); fsum += fwv[x]; }
    const float finv = 1.0f / fsum;

    int   ve[NW]; float bfw[NW];
    #pragma unroll
    for (int w = 0; w < NW; w++){
        int r = rp.ve[e][w];
        ve[w] = r;
        float bf = (r == e) ? 1.0f : 1.0f / (1.0f + __expf(-betas[e * NE + r]));
        bfw[w] = bf * invtemp;
    }

    float cT[16][4];
    #pragma unroll
    for (int f = 0; f < 16; f++){
        cT[f][0] = 0.f; cT[f][1] = 0.f; cT[f][2] = 0.f; cT[f][3] = 0.f;
    }

    const int c0 = (lane & 3) * 2;
    const int rl = wid * 16 + (lane >> 2);   // thread rows rl, rl+8
    const int m8 = lane >> 3, w8 = lane & 7; // ldsm addressing

    // prefetch global chunks 0 and 1 (ve is x-independent)
    {
        const size_t pb0 = (size_t)((0 * NE + ve[0]) * NB + b) * (NP * ND);
        issue_chunk(smb, 0, g_v16 + pb0, tid);
        cp_commit();
        issue_chunk(smb, 1, g_v16 + pb0 + (size_t)KC * ND, tid);
        cp_commit();
    }

    for (int x = 0; x < NDIRS; x++){
        __syncthreads();   // previous x fully done with sS before rebuild

        // ---- prologue: s, q, minmax, mx ----
        #pragma unroll
        for (int i = 0; i < 6; i++){
            int idx = tid + i * NT;
            int w = idx >> 8, k = idx & 255;
            sS[idx] = Kf[(((x * NE + ve[w]) * NB + b) << 8) + k] * bfw[w];
        }
        if (tid < MT)
            sQ[tid] = Q[(((x * NE + e) * NB + b) << 8) + m0 + tid];
        __syncthreads();

        float lmax = -1e30f, lmin = 1e30f;
        #pragma unroll
        for (int i = 0; i < 6; i++){
            float v = sS[tid + i * NT];
            lmax = fmaxf(lmax, v); lmin = fminf(lmin, v);
        }
        #pragma unroll
        for (int off = 16; off; off >>= 1){
            lmax = fmaxf(lmax, __shfl_xor_sync(0xffffffffu, lmax, off));
            lmin = fminf(lmin, __shfl_xor_sync(0xffffffffu, lmin, off));
        }
        if (lane == 0){ sRed[wid] = lmax; sRed[4 + wid] = lmin; }
        __syncthreads();
        if (tid == 0){
            float a = -1e30f, c = 1e30f;
            #pragma unroll
            for (int i = 0; i < 4; i++){ a = fmaxf(a, sRed[i]); c = fminf(c, sRed[4 + i]); }
            sMM[0] = a; sMM[1] = c;
        }
        __syncthreads();
        if (tid < MT){
            float q = sQ[tid];
            sMx[tid] = fmaxf(q * sMM[0], q * sMM[1]);
        }
        __syncthreads();

        const float qa = sQ[rl] * LOG2E;
        const float qb = sQ[rl + 8] * LOG2E;
        const float ma = -sMx[rl] * LOG2E;
        const float mb = -sMx[rl + 8] * LOG2E;

        float cX[16][4];
        #pragma unroll
        for (int f = 0; f < 16; f++){
            cX[f][0] = 0.f; cX[f][1] = 0.f; cX[f][2] = 0.f; cX[f][3] = 0.f;
        }
        float den0 = 0.f, den1 = 0.f;

        // ---- chunk loop: 3-stage ring, one barrier per chunk ----
        for (int ch = 0; ch < NCH; ch++){
            const int g = x * NCH + ch;
            cp_wait<1>();
            __syncthreads();     // stage g%3 ready; stage (g+2)%3 now free

            {
                const int g2 = g + 2;
                if (g2 < NG){
                    const int xg = g2 / NCH;
                    const int kt = (g2 % NCH) * KC;
                    const size_t pb = (size_t)((xg * NE + ve[kt >> 8]) * NB + b) * (NP * ND)
                                      + (size_t)(kt & 255) * ND;
                    issue_chunk(smb, g2 % NST, g_v16 + pb, tid);
                }
                cp_commit();     // empty group near the end keeps counts uniform
            }

            const int st = g % NST;
            const int koff = ch * KC;

            #pragma unroll
            for (int k16 = 0; k16 < 4; k16++){
                const int kb = k16 * 16;

                // ---- A fragments (rows rl, rl+8): exp -> fp16 (1-term) ----
                float sv0 = sS[koff + kb + c0];
                float sv1 = sS[koff + kb + c0 + 1];
                float sv2 = sS[koff + kb + c0 + 8];
                float sv3 = sS[koff + kb + c0 + 9];

                float ea0 = ex2f(fmaf(qa, sv0, ma));
                float ea1 = ex2f(fmaf(qa, sv1, ma));
                float ea2 = ex2f(fmaf(qa, sv2, ma));
                float ea3 = ex2f(fmaf(qa, sv3, ma));
                float eb0 = ex2f(fmaf(qb, sv0, mb));
                float eb1 = ex2f(fmaf(qb, sv1, mb));
                float eb2 = ex2f(fmaf(qb, sv2, mb));
                float eb3 = ex2f(fmaf(qb, sv3, mb));
                den0 += (ea0 + ea1) + (ea2 + ea3);
                den1 += (eb0 + eb1) + (eb2 + eb3);

                uint32_t ah0 = pack_h2(ea0, ea1);
                uint32_t ah1 = pack_h2(eb0, eb1);
                uint32_t ah2 = pack_h2(ea2, ea3);
                uint32_t ah3 = pack_h2(eb2, eb3);

                // ---- B fragments + MMA over all 8 n16 blocks (single fp16 plane) ----
                const int kr = kb + (m8 & 1) * 8 + w8;
                #pragma unroll
                for (int nb = 0; nb < 8; nb++){
                    const int cc = nb * 2 + (m8 >> 1);
                    const uint32_t boff = (uint32_t)(kr * 256 + ((cc ^ (kr & 7)) << 4));
                    uint32_t b0, b1, b2, b3;
                    ldsm4t(b0, b1, b2, b3, smb + SM_V(st) + boff);
                    mma16816(cX[2 * nb],     ah0, ah1, ah2, ah3, b0, b1);
                    mma16816(cX[2 * nb + 1], ah0, ah1, ah2, ah3, b2, b3);
                }
            }
        }

        // ---- fold x into fused accumulator: cT += (wx/den_row) * cX ----
        den0 += __shfl_xor_sync(0xffffffffu, den0, 1);
        den0 += __shfl_xor_sync(0xffffffffu, den0, 2);
        den1 += __shfl_xor_sync(0xffffffffu, den1, 1);
        den1 += __shfl_xor_sync(0xffffffffu, den1, 2);
        const float wx = fwv[x] * finv;
        const float la = wx / den0;
        const float lb = wx / den1;
        #pragma unroll
        for (int f = 0; f < 16; f++){
            cT[f][0] = fmaf(la, cX[f][0], cT[f][0]);
            cT[f][1] = fmaf(la, cX[f][1], cT[f][1]);
            cT[f][2] = fmaf(lb, cX[f][2], cT[f][2]);
            cT[f][3] = fmaf(lb, cX[f][3], cT[f][3]);
        }
    }

    // drain outstanding async copies before CTA exit (tail groups are empty)
    cp_wait<0>();

    // ---- epilogue ----
    {
        const int row = m0 + rl;
        float* obase = out + ((size_t)b * (NE * NP) + (size_t)e * NP + row) * ND;
        #pragma unroll
        for (int f = 0; f < 16; f++){
            const int nb = f >> 1, t = f & 1;
            const int col = nb * 16 + t * 8 + (lane & 3) * 2;
            float2 v0 = {cT[f][0], cT[f][1]};
            float2 v1 = {cT[f][2], cT[f][3]};
            *(float2*)(obase + col) = v0;
            *(float2*)(obase + (size_t)8 * ND + col) = v1;
        }
    }
}

// ---- host: replicate numpy route construction exactly ----
static void compute_routes(RoutesP* rp)
{
    float coords[NE];
    for (int i = 0; i < NE; i++){
        double xx = (double)i / 15.0;
        if (xx < 1e-6)       xx = 1e-6;
        if (xx > 1.0 - 1e-6) xx = 1.0 - 1e-6;
        double val = 0.0, f = 0.5;
        for (int d = 0; d < 8; d++){
            xx *= 3.0;
            int dig = (int)xx;
            xx -= (double)dig;
            if (dig == 2) val += f;
            f *= 0.5;
        }
        coords[i] = (float)val;
    }
    for (int i = 0; i < NE; i++){
        float dist[NE]; int idx[NE];
        for (int j = 0; j < NE; j++){ dist[j] = fabsf(coords[j] - coords[i]); idx[j] = j; }
        for (int a = 1; a < NE; a++){
            float dv = dist[a]; int iv = idx[a];
            int c = a - 1;
            while (c >= 0 && dist[c] > dv){
                dist[c + 1] = dist[c]; idx[c + 1] = idx[c]; c--;
            }
            dist[c + 1] = dv; idx[c + 1] = iv;
        }
        int r3[NW] = { idx[0], idx[1], idx[2] };
        for (int a = 0; a < NW; a++)
            for (int c = a + 1; c < NW; c++)
                if (r3[c] < r3[a]){ int t = r3[a]; r3[a] = r3[c]; r3[c] = t; }
        for (int w = 0; w < NW; w++) rp->ve[i][w] = r3[w];
    }
}

extern "C" void kernel_launch(void* const* d_in, const int* in_sizes, int n_in,
                              void* d_out, int out_size)
{
    (void)in_sizes; (void)n_in; (void)out_size;
    cudaFuncSetAttribute(cantor_attn_mma,
                         cudaFuncAttributeMaxDynamicSharedMemorySize, SMEM_TOTAL);

    RoutesP rp;
    compute_routes(&rp);

    // 1) V -> fp16 plane (elementwise)
    const size_t nV = (size_t)NDIRS * NE * NB * NP * ND;   // 10,485,760
    vsplit_kernel<<<(unsigned)(nV / (256 * 8)), 256>>>((const float*)d_in[2]);

    // 2) fused attention, mma.sync fp16 1-term, 2 CTAs/SM
    dim3 g2(NP / MT, NB, NE);   // (4, 4, 16) = 256 blocks
    cantor_attn_mma<<<g2, NT, SMEM_TOTAL>>>(
        (const float*)d_in[0],   // Q_aff
        (const float*)d_in[1],   // K_aff
        (const float*)d_in[3],   // betas
        (const float*)d_in[4],   // temperature
        (const float*)d_in[5],   // fusion_weights
        (float*)d_out, rp);
}

// round 12
// speedup vs baseline: 1.0685x; 1.0685x over previous
#include <cuda_runtime.h>
#include <cuda_fp16.h>
#include <math.h>
#include <stdint.h>

#define NDIRS 5
#define NE    16
#define NW    3
#define ND    128
#define NP    256
#define NB    4
#define WK    768
#define MT    128         // rows per CTA (8 warps x 16)
#define NT    256         // threads per CTA
#define KC    128         // k per chunk (2x bigger: fewer barriers, longer bursts)
#define NCH   (WK/KC)     // 6 chunks per x
#define NG    (NDIRS*NCH) // 30 global chunks
#define NST   3
#define LOG2E 1.4426950408889634f

struct RoutesP { int ve[NE][NW]; };

// V as fp16, [x][e][b][p][d] (elementwise convert, same layout as V)
__device__ __align__(16) __half g_v16[(size_t)NDIRS*NE*NB*NP*ND];

// ---------------- dynamic smem layout ----------------
// stage s: [KC][128] fp16 tile (32KB), XOR-swizzled 16B chunks
#define SM_V(s)   ((s)*32768)
#define SM_S      (NST*32768)          // f32[5][768] = 15360B
#define SM_Q      (SM_S + 15360)       // f32[5][128] = 2560B
#define SM_MX     (SM_Q + 2560)        // f32[5][128] = 2560B
#define SM_RED    (SM_MX + 2560)       // f32[5][16]  = 320B
#define SM_MM     (SM_RED + 320)       // f32[5][2]
#define SMEM_TOTAL (SM_MM + 64)        // ~116.4 KB

// ---------------- helpers ----------------
__device__ __forceinline__ uint32_t smem_u32(const void* p){
    uint32_t a;
    asm("{ .reg .u64 t; cvta.to.shared.u64 t, %1; cvt.u32.u64 %0, t; }" : "=r"(a) : "l"(p));
    return a;
}
__device__ __forceinline__ float ex2f(float x){
    float r; asm("ex2.approx.ftz.f32 %0, %1;" : "=f"(r) : "f"(x)); return r;
}
// pack two f32 -> f16x2 (lo=a, hi=b)
__device__ __forceinline__ uint32_t pack_h2(float a, float b){
    uint32_t r;
    asm("cvt.rn.f16x2.f32 %0, %2, %1;" : "=r"(r) : "f"(a), "f"(b));
    return r;
}
__device__ __forceinline__ void ldsm4t(uint32_t& r0, uint32_t& r1, uint32_t& r2, uint32_t& r3,
                                       uint32_t addr){
    asm volatile("ldmatrix.sync.aligned.m8n8.x4.trans.shared.b16 {%0,%1,%2,%3}, [%4];"
                 : "=r"(r0), "=r"(r1), "=r"(r2), "=r"(r3) : "r"(addr));
}
__device__ __forceinline__ void mma16816(float* c,
                                         uint32_t a0, uint32_t a1, uint32_t a2, uint32_t a3,
                                         uint32_t b0, uint32_t b1){
    asm volatile("mma.sync.aligned.m16n8k16.row.col.f32.f16.f16.f32 "
                 "{%0,%1,%2,%3}, {%4,%5,%6,%7}, {%8,%9}, {%0,%1,%2,%3};"
                 : "+f"(c[0]), "+f"(c[1]), "+f"(c[2]), "+f"(c[3])
                 : "r"(a0), "r"(a1), "r"(a2), "r"(a3), "r"(b0), "r"(b1));
}
__device__ __forceinline__ void cp16(uint32_t dst, const void* src){
    asm volatile("cp.async.cg.shared.global [%0], [%1], 16;" :: "r"(dst), "l"(src));
}
__device__ __forceinline__ void cp_commit(){ asm volatile("cp.async.commit_group;" ::: "memory"); }
template<int N> __device__ __forceinline__ void cp_wait(){
    asm volatile("cp.async.wait_group %0;" :: "n"(N) : "memory");
}

// stage a KC x 128 fp16 chunk into smem stage st with 16B-chunk XOR swizzle
__device__ __forceinline__ void issue_chunk(uint32_t smb, int st,
                                            const __half* __restrict__ src,
                                            int tid){
    #pragma unroll
    for (int i = 0; i < 8; i++){
        int cid = tid + i * NT;               // 0..2047 16B chunks
        int row = cid >> 4, c = cid & 15;
        uint32_t soff = (uint32_t)(row * 256 + ((c ^ (row & 7)) << 4));
        cp16(smb + SM_V(st) + soff, src + row * ND + c * 8);
    }
}

// ---------------- pre-kernel: elementwise V -> fp16 ----------------
__global__ __launch_bounds__(256)
void vsplit_kernel(const float* __restrict__ V){
    size_t i = ((size_t)blockIdx.x * 256 + threadIdx.x) * 8;
    float4 v0 = *(const float4*)(V + i);
    float4 v1 = *(const float4*)(V + i + 4);
    uint4 o;
    o.x = pack_h2(v0.x, v0.y);
    o.y = pack_h2(v0.z, v0.w);
    o.z = pack_h2(v1.x, v1.y);
    o.w = pack_h2(v1.z, v1.w);
    *(uint4*)((char*)g_v16 + i * 2) = o;
}

// ---------------- main kernel ----------------
__global__ __launch_bounds__(NT, 1)
void cantor_attn_mma(const float* __restrict__ Q,
                     const float* __restrict__ Kf,
                     const float* __restrict__ betas,
                     const float* __restrict__ temp,
                     const float* __restrict__ fw,
                     float* __restrict__ out,
                     RoutesP rp)
{
    extern __shared__ char sm[];
    const uint32_t smb = smem_u32(sm);
    float* sS  = (float*)(sm + SM_S);    // [5][768]
    float* sQ  = (float*)(sm + SM_Q);    // [5][128]
    float* sMx = (float*)(sm + SM_MX);   // [5][128]
    float* sRed= (float*)(sm + SM_RED);  // [5][16]
    float* sMM = (float*)(sm + SM_MM);   // [5][2]

    const int tid  = threadIdx.x;
    const int lane = tid & 31;
    const int wid  = tid >> 5;          // 8 warps, warp wid owns rows wid*16..+15
    const int e  = blockIdx.z;
    const int b  = blockIdx.y;
    const int m0 = blockIdx.x * MT;

    const float invtemp = 1.0f / (fabsf(temp[0]) + 1e-6f);

    // fusion softmax weights
    float fwv[NDIRS], fm = -1e30f;
    #pragma unroll
    for (int x = 0; x < NDIRS; x++){ fwv[x] = fw[x]; fm = fmaxf(fm, fwv[x]); }
    float fsum = 0.0f;
    #pragma unroll
    for (int x = 0; x < NDIRS; x++){ fwv[x] = __expf(fwv[x] - fm); fsum += fwv[x]; }
    const float finv = 1.0f / fsum;

    int   ve[NW]; float bfw[NW];
    #pragma unroll
    for (int w = 0; w < NW; w++){
        int r = rp.ve[e][w];
        ve[w] = r;
        float bf = (r == e) ? 1.0f : 1.0f / (1.0f + __expf(-betas[e * NE + r]));
        bfw[w] = bf * invtemp;
    }

    const int c0 = (lane & 3) * 2;
    const int rl = wid * 16 + (lane >> 2);   // thread rows rl, rl+8
    const int m8 = lane >> 3, w8 = lane & 7; // ldsm addressing

    // prefetch global chunks 0 and 1 (x=0, route page ve[0])
    {
        const size_t pb0 = (size_t)((0 * NE + ve[0]) * NB + b) * (NP * ND);
        issue_chunk(smb, 0, g_v16 + pb0, tid);
        cp_commit();
        issue_chunk(smb, 1, g_v16 + pb0 + (size_t)KC * ND, tid);
        cp_commit();
    }

    // ======== batched prologue: all 5 x upfront ========
    // sS[x][768] scaled-K vectors
    #pragma unroll
    for (int i = 0; i < 15; i++){
        int idx = tid + i * NT;              // 0..3839
        int blk = idx >> 8;                  // 0..14
        int x = blk / 3, w = blk % 3;
        int k = idx & 255;
        sS[idx] = Kf[(((x * NE + ve[w]) * NB + b) << 8) + k] * bfw[w];
    }
    // sQ[x][128]
    #pragma unroll
    for (int i = 0; i < 3; i++){
        int idx = tid + i * NT;
        if (idx < NDIRS * MT){
            int x = idx >> 7, r = idx & 127;
            sQ[idx] = Q[(((x * NE + e) * NB + b) << 8) + m0 + r];
        }
    }
    __syncthreads();

    // per-x min/max of s
    #pragma unroll
    for (int x = 0; x < NDIRS; x++){
        float lmax = -1e30f, lmin = 1e30f;
        #pragma unroll
        for (int i = 0; i < 3; i++){
            float v = sS[x * WK + tid + i * NT];
            lmax = fmaxf(lmax, v); lmin = fminf(lmin, v);
        }
        #pragma unroll
        for (int off = 16; off; off >>= 1){
            lmax = fmaxf(lmax, __shfl_xor_sync(0xffffffffu, lmax, off));
            lmin = fminf(lmin, __shfl_xor_sync(0xffffffffu, lmin, off));
        }
        if (lane == 0){ sRed[x * 16 + wid] = lmax; sRed[x * 16 + 8 + wid] = lmin; }
    }
    __syncthreads();
    if (tid < NDIRS){
        float a = -1e30f, c = 1e30f;
        #pragma unroll
        for (int i = 0; i < 8; i++){
            a = fmaxf(a, sRed[tid * 16 + i]);
            c = fminf(c, sRed[tid * 16 + 8 + i]);
        }
        sMM[tid * 2] = a; sMM[tid * 2 + 1] = c;
    }
    __syncthreads();
    // sMx[x][r] = exact row max
    #pragma unroll
    for (int i = 0; i < 3; i++){
        int idx = tid + i * NT;
        if (idx < NDIRS * MT){
            int x = idx >> 7;
            float q = sQ[idx];
            sMx[idx] = fmaxf(q * sMM[x * 2], q * sMM[x * 2 + 1]);
        }
    }
    __syncthreads();

    // ======== main x / chunk loop ========
    float cT[16][4];
    #pragma unroll
    for (int f = 0; f < 16; f++){
        cT[f][0] = 0.f; cT[f][1] = 0.f; cT[f][2] = 0.f; cT[f][3] = 0.f;
    }

    int g = 0;
    for (int x = 0; x < NDIRS; x++){
        const float qa = sQ[x * MT + rl] * LOG2E;
        const float qb = sQ[x * MT + rl + 8] * LOG2E;
        const float ma = -sMx[x * MT + rl] * LOG2E;
        const float mb = -sMx[x * MT + rl + 8] * LOG2E;

        float cX[16][4];
        #pragma unroll
        for (int f = 0; f < 16; f++){
            cX[f][0] = 0.f; cX[f][1] = 0.f; cX[f][2] = 0.f; cX[f][3] = 0.f;
        }
        float den0 = 0.f, den1 = 0.f;

        for (int ch = 0; ch < NCH; ch++){
            cp_wait<1>();
            __syncthreads();     // stage g%3 ready; stage (g+2)%3 now free

            {
                const int g2 = g + 2;
                if (g2 < NG){
                    const int xg = g2 / NCH;
                    const int kt = (g2 % NCH) * KC;
                    const size_t pb = (size_t)((xg * NE + ve[kt >> 8]) * NB + b) * (NP * ND)
                                      + (size_t)(kt & 255) * ND;
                    issue_chunk(smb, g2 % NST, g_v16 + pb, tid);
                }
                cp_commit();     // empty group near the end keeps counts uniform
            }

            const int st = g % NST;
            const int soff = x * WK + ch * KC;

            #pragma unroll
            for (int k16 = 0; k16 < KC / 16; k16++){
                const int kb = k16 * 16;

                // ---- A fragments (rows rl, rl+8): exp -> fp16 (1-term) ----
                float sv0 = sS[soff + kb + c0];
                float sv1 = sS[soff + kb + c0 + 1];
                float sv2 = sS[soff + kb + c0 + 8];
                float sv3 = sS[soff + kb + c0 + 9];

                float ea0 = ex2f(fmaf(qa, sv0, ma));
                float ea1 = ex2f(fmaf(qa, sv1, ma));
                float ea2 = ex2f(fmaf(qa, sv2, ma));
                float ea3 = ex2f(fmaf(qa, sv3, ma));
                float eb0 = ex2f(fmaf(qb, sv0, mb));
                float eb1 = ex2f(fmaf(qb, sv1, mb));
                float eb2 = ex2f(fmaf(qb, sv2, mb));
                float eb3 = ex2f(fmaf(qb, sv3, mb));
                den0 += (ea0 + ea1) + (ea2 + ea3);
                den1 += (eb0 + eb1) + (eb2 + eb3);

                uint32_t ah0 = pack_h2(ea0, ea1);
                uint32_t ah1 = pack_h2(eb0, eb1);
                uint32_t ah2 = pack_h2(ea2, ea3);
                uint32_t ah3 = pack_h2(eb2, eb3);

                // ---- B fragments + MMA over all 8 n16 blocks (single fp16 plane) ----
                const int kr = kb + (m8 & 1) * 8 + w8;
                #pragma unroll
                for (int nb = 0; nb < 8; nb++){
                    const int cc = nb * 2 + (m8 >> 1);
                    const uint32_t boff = (uint32_t)(kr * 256 + ((cc ^ (kr & 7)) << 4));
                    uint32_t b0, b1, b2, b3;
                    ldsm4t(b0, b1, b2, b3, smb + SM_V(st) + boff);
                    mma16816(cX[2 * nb],     ah0, ah1, ah2, ah3, b0, b1);
                    mma16816(cX[2 * nb + 1], ah0, ah1, ah2, ah3, b2, b3);
                }
            }
            g++;
        }

        // ---- fold x into fused accumulator: cT += (wx/den_row) * cX ----
        den0 += __shfl_xor_sync(0xffffffffu, den0, 1);
        den0 += __shfl_xor_sync(0xffffffffu, den0, 2);
        den1 += __shfl_xor_sync(0xffffffffu, den1, 1);
        den1 += __shfl_xor_sync(0xffffffffu, den1, 2);
        const float wx = fwv[x] * finv;
        const float la = wx / den0;
        const float lb = wx / den1;
        #pragma unroll
        for (int f = 0; f < 16; f++){
            cT[f][0] = fmaf(la, cX[f][0], cT[f][0]);
            cT[f][1] = fmaf(la, cX[f][1], cT[f][1]);
            cT[f][2] = fmaf(lb, cX[f][2], cT[f][2]);
            cT[f][3] = fmaf(lb, cX[f][3], cT[f][3]);
        }
    }

    // drain outstanding async copies before CTA exit (tail groups are empty)
    cp_wait<0>();

    // ---- epilogue ----
    {
        const int row = m0 + rl;
        float* obase = out + ((size_t)b * (NE * NP) + (size_t)e * NP + row) * ND;
        #pragma unroll
        for (int f = 0; f < 16; f++){
            const int nb = f >> 1, t = f & 1;
            const int col = nb * 16 + t * 8 + (lane & 3) * 2;
            float2 v0 = {cT[f][0], cT[f][1]};
            float2 v1 = {cT[f][2], cT[f][3]};
            *(float2*)(obase + col) = v0;
            *(float2*)(obase + (size_t)8 * ND + col) = v1;
        }
    }
}

// ---- host: replicate numpy route construction exactly ----
static void compute_routes(RoutesP* rp)
{
    float coords[NE];
    for (int i = 0; i < NE; i++){
        double xx = (double)i / 15.0;
        if (xx < 1e-6)       xx = 1e-6;
        if (xx > 1.0 - 1e-6) xx = 1.0 - 1e-6;
        double val = 0.0, f = 0.5;
        for (int d = 0; d < 8; d++){
            xx *= 3.0;
            int dig = (int)xx;
            xx -= (double)dig;
            if (dig == 2) val += f;
            f *= 0.5;
        }
        coords[i] = (float)val;
    }
    for (int i = 0; i < NE; i++){
        float dist[NE]; int idx[NE];
        for (int j = 0; j < NE; j++){ dist[j] = fabsf(coords[j] - coords[i]); idx[j] = j; }
        for (int a = 1; a < NE; a++){
            float dv = dist[a]; int iv = idx[a];
            int c = a - 1;
            while (c >= 0 && dist[c] > dv){
                dist[c + 1] = dist[c]; idx[c + 1] = idx[c]; c--;
            }
            dist[c + 1] = dv; idx[c + 1] = iv;
        }
        int r3[NW] = { idx[0], idx[1], idx[2] };
        for (int a = 0; a < NW; a++)
            for (int c = a + 1; c < NW; c++)
                if (r3[c] < r3[a]){ int t = r3[a]; r3[a] = r3[c]; r3[c] = t; }
        for (int w = 0; w < NW; w++) rp->ve[i][w] = r3[w];
    }
}

extern "C" void kernel_launch(void* const* d_in, const int* in_sizes, int n_in,
                              void* d_out, int out_size)
{
    (void)in_sizes; (void)n_in; (void)out_size;
    cudaFuncSetAttribute(cantor_attn_mma,
                         cudaFuncAttributeMaxDynamicSharedMemorySize, SMEM_TOTAL);

    RoutesP rp;
    compute_routes(&rp);

    // 1) V -> fp16 plane (elementwise)
    const size_t nV = (size_t)NDIRS * NE * NB * NP * ND;   // 10,485,760
    vsplit_kernel<<<(unsigned)(nV / (256 * 8)), 256>>>((const float*)d_in[2]);

    // 2) fused attention, mma.sync fp16 1-term, batched prologue, KC=128
    dim3 g2(NP / MT, NB, NE);   // (2, 4, 16) = 128 blocks
    cantor_attn_mma<<<g2, NT, SMEM_TOTAL>>>(
        (const float*)d_in[0],   // Q_aff
        (const float*)d_in[1],   // K_aff
        (const float*)d_in[3],   // betas
        (const float*)d_in[4],   // temperature
        (const float*)d_in[5],   // fusion_weights
        (float*)d_out, rp);
}